// round 5
// baseline (speedup 1.0000x reference)
#include <cuda_runtime.h>
#include <cstdint>

#define U_CNT 100000
#define I_CNT 50000
#define DIM   64
#define N_CNT 150000
#define NNZ_E 1000000

#define SCAN_B 1024
#define NBLK   ((N_CNT + SCAN_B - 1) / SCAN_B)   // 147

// ---- static device scratch (no runtime allocation) ----
__device__ int  g_rowptr_a[N_CNT + 1];
__device__ int  g_rowptr_r[N_CNT + 1];
__device__ int  g_cursor_a[N_CNT];
__device__ int  g_cursor_r[N_CNT];
__device__ unsigned int g_tile_a[NBLK];   // decoupled-lookback: (value<<2)|status
__device__ unsigned int g_tile_r[NBLK];   // status: 0 invalid, 1 aggregate, 2 prefix
__device__ int2 g_sorted_a[NNZ_E];        // (col, val bits) grouped by row
__device__ int2 g_sorted_r[NNZ_E];

static __device__ __forceinline__ const float4* ego_row(
    const float* __restrict__ ue, const float* __restrict__ ie, int n) {
    return (n < U_CNT)
        ? reinterpret_cast<const float4*>(ue + (size_t)n * DIM)
        : reinterpret_cast<const float4*>(ie + (size_t)(n - U_CNT) * DIM);
}

static __device__ __forceinline__ void fma4(float4& acc, float v, const float4& x) {
    acc.x = fmaf(v, x.x, acc.x);
    acc.y = fmaf(v, x.y, acc.y);
    acc.z = fmaf(v, x.z, acc.z);
    acc.w = fmaf(v, x.w, acc.w);
}

// K0: zero counters + lookback state (each graph replay must start clean).
__global__ void lgcn_zero() {
    int i = blockIdx.x * blockDim.x + threadIdx.x;
    if (i < N_CNT) { g_rowptr_a[i] = 0; g_rowptr_r[i] = 0; }
    if (i < NBLK)  { g_tile_a[i] = 0u;  g_tile_r[i] = 0u; }
}

// K1: row histogram for both matrices.
__global__ void lgcn_hist(const int* __restrict__ a_rows,
                          const int* __restrict__ r_rows) {
    int i = blockIdx.x * blockDim.x + threadIdx.x;
    if (i < NNZ_E) {
        atomicAdd(&g_rowptr_a[__ldg(&a_rows[i])], 1);
        atomicAdd(&g_rowptr_r[__ldg(&r_rows[i])], 1);
    }
}

// K2: single-pass exclusive scan with decoupled lookback. grid = (NBLK, 2).
__global__ void lgcn_scan() {
    int  m = blockIdx.y;
    int  b = blockIdx.x;
    int  t = threadIdx.x;
    int* cnt = m ? g_rowptr_r : g_rowptr_a;
    int* cur = m ? g_cursor_r : g_cursor_a;
    unsigned int* st = m ? g_tile_r : g_tile_a;

    __shared__ int s[SCAN_B];
    __shared__ int ex_prefix;

    int i = b * SCAN_B + t;
    int v = (i < N_CNT) ? cnt[i] : 0;
    s[t] = v;
    __syncthreads();
    #pragma unroll
    for (int off = 1; off < SCAN_B; off <<= 1) {
        int u = (t >= off) ? s[t - off] : 0;
        __syncthreads();
        s[t] += u;
        __syncthreads();
    }
    int incl  = s[t];
    int total = s[SCAN_B - 1];

    if (t == 0) {
        if (b == 0) {
            ex_prefix = 0;
            atomicExch(&st[0], ((unsigned int)total << 2) | 2u);
        } else {
            atomicExch(&st[b], ((unsigned int)total << 2) | 1u);
            int run = 0;
            for (int j = b - 1; j >= 0; j--) {
                unsigned int x;
                do { x = atomicAdd(&st[j], 0u); } while ((x & 3u) == 0u);
                run += (int)(x >> 2);
                if ((x & 3u) == 2u) break;
            }
            ex_prefix = run;
            atomicExch(&st[b], ((unsigned int)(run + total) << 2) | 2u);
        }
    }
    __syncthreads();

    if (i < N_CNT) {
        int val = ex_prefix + incl - v;   // global exclusive prefix
        cnt[i] = val;
        cur[i] = val;
    }
    if (b == NBLK - 1 && t == SCAN_B - 1) cnt[N_CNT] = NNZ_E;
}

// K3: scatter (col, val) into row-grouped order. 1 edge per matrix per thread
// (latency-bound kernel: maximize concurrent chains / occupancy).
__global__ void lgcn_scatter(const int*  __restrict__ a_rows,
                             const int*  __restrict__ a_cols,
                             const float* __restrict__ a_vals,
                             const int*  __restrict__ r_rows,
                             const int*  __restrict__ r_cols,
                             const float* __restrict__ r_vals) {
    int i = blockIdx.x * blockDim.x + threadIdx.x;
    if (i >= NNZ_E) return;
    int ra = __ldg(&a_rows[i]);
    int rr = __ldg(&r_rows[i]);
    int ca = __ldg(&a_cols[i]);
    int cr = __ldg(&r_cols[i]);
    float va = __ldg(&a_vals[i]);
    float vr = __ldg(&r_vals[i]);
    int pa = atomicAdd(&g_cursor_a[ra], 1);
    int pr = atomicAdd(&g_cursor_r[rr], 1);
    g_sorted_a[pa] = make_int2(ca, __float_as_int(va));
    g_sorted_r[pr] = make_int2(cr, __float_as_int(vr));
}

// Tail reduction: handles any remaining edges with unroll-4 + batched loads.
static __device__ __forceinline__ float4 row_tail(
    const int2* __restrict__ sorted, int i, int e, int q,
    const float* __restrict__ ue, const float* __restrict__ ie, float4 acc) {
    for (; i + 4 <= e; i += 4) {
        int2 c0 = __ldg(&sorted[i]);
        int2 c1 = __ldg(&sorted[i + 1]);
        int2 c2 = __ldg(&sorted[i + 2]);
        int2 c3 = __ldg(&sorted[i + 3]);
        float4 x0 = __ldg(&ego_row(ue, ie, c0.x)[q]);
        float4 x1 = __ldg(&ego_row(ue, ie, c1.x)[q]);
        float4 x2 = __ldg(&ego_row(ue, ie, c2.x)[q]);
        float4 x3 = __ldg(&ego_row(ue, ie, c3.x)[q]);
        fma4(acc, __int_as_float(c0.y), x0);
        fma4(acc, __int_as_float(c1.y), x1);
        fma4(acc, __int_as_float(c2.y), x2);
        fma4(acc, __int_as_float(c3.y), x3);
    }
    if (i < e) {
        int2 c0 = __ldg(&sorted[i]);
        int2 c1 = (i + 1 < e) ? __ldg(&sorted[i + 1]) : make_int2(0, 0);
        int2 c2 = (i + 2 < e) ? __ldg(&sorted[i + 2]) : make_int2(0, 0);
        float4 x0 = __ldg(&ego_row(ue, ie, c0.x)[q]);
        fma4(acc, __int_as_float(c0.y), x0);
        if (i + 1 < e) {
            float4 x1 = __ldg(&ego_row(ue, ie, c1.x)[q]);
            fma4(acc, __int_as_float(c1.y), x1);
        }
        if (i + 2 < e) {
            float4 x2 = __ldg(&ego_row(ue, ie, c2.x)[q]);
            fma4(acc, __int_as_float(c2.y), x2);
        }
    }
    return acc;
}

// K4: per-row gather SpMM + full output emit. The A and R edge loops are
// interleaved in the main body: 8 independent gathers in flight per iteration.
__global__ void lgcn_gather(const float* __restrict__ ue,
                            const float* __restrict__ ie,
                            float* __restrict__ out) {
    int idx = blockIdx.x * blockDim.x + threadIdx.x;
    if (idx >= N_CNT * 16) return;
    int n = idx >> 4;
    int q = idx & 15;

    float4 e = __ldg(&ego_row(ue, ie, n)[q]);

    int ia = __ldg(&g_rowptr_a[n]);
    int ea = __ldg(&g_rowptr_a[n + 1]);
    int ir = __ldg(&g_rowptr_r[n]);
    int er = __ldg(&g_rowptr_r[n + 1]);

    float4 a = make_float4(0.f, 0.f, 0.f, 0.f);
    float4 r = make_float4(0.f, 0.f, 0.f, 0.f);

    // interleaved main loop: 4 edges from each matrix per iteration
    while (ia + 4 <= ea && ir + 4 <= er) {
        int2 a0 = __ldg(&g_sorted_a[ia]);
        int2 a1 = __ldg(&g_sorted_a[ia + 1]);
        int2 a2 = __ldg(&g_sorted_a[ia + 2]);
        int2 a3 = __ldg(&g_sorted_a[ia + 3]);
        int2 r0 = __ldg(&g_sorted_r[ir]);
        int2 r1 = __ldg(&g_sorted_r[ir + 1]);
        int2 r2 = __ldg(&g_sorted_r[ir + 2]);
        int2 r3 = __ldg(&g_sorted_r[ir + 3]);
        float4 xa0 = __ldg(&ego_row(ue, ie, a0.x)[q]);
        float4 xa1 = __ldg(&ego_row(ue, ie, a1.x)[q]);
        float4 xa2 = __ldg(&ego_row(ue, ie, a2.x)[q]);
        float4 xa3 = __ldg(&ego_row(ue, ie, a3.x)[q]);
        float4 xr0 = __ldg(&ego_row(ue, ie, r0.x)[q]);
        float4 xr1 = __ldg(&ego_row(ue, ie, r1.x)[q]);
        float4 xr2 = __ldg(&ego_row(ue, ie, r2.x)[q]);
        float4 xr3 = __ldg(&ego_row(ue, ie, r3.x)[q]);
        fma4(a, __int_as_float(a0.y), xa0);
        fma4(a, __int_as_float(a1.y), xa1);
        fma4(a, __int_as_float(a2.y), xa2);
        fma4(a, __int_as_float(a3.y), xa3);
        fma4(r, __int_as_float(r0.y), xr0);
        fma4(r, __int_as_float(r1.y), xr1);
        fma4(r, __int_as_float(r2.y), xr2);
        fma4(r, __int_as_float(r3.y), xr3);
        ia += 4;
        ir += 4;
    }
    a = row_tail(g_sorted_a, ia, ea, q, ue, ie, a);
    r = row_tail(g_sorted_r, ir, er, q, ue, ie, r);

    size_t sbase = (size_t)N_CNT * DIM + (size_t)n * 4 * DIM;
    size_t pbase = sbase + (size_t)N_CNT * 4 * DIM;
    float4* s = reinterpret_cast<float4*>(out + sbase);
    float4* p = reinterpret_cast<float4*>(out + pbase);
    __stcs(&s[q],      e);    // stacked slot 0
    __stcs(&s[16 + q], a);    // slots 1..3 identical (reference never updates ego)
    __stcs(&s[32 + q], a);
    __stcs(&s[48 + q], a);
    __stcs(&p[q],      e);
    __stcs(&p[16 + q], r);
    __stcs(&p[32 + q], r);
    __stcs(&p[48 + q], r);

    float4 m = make_float4((e.x + 3.f * a.x) * 0.25f,
                           (e.y + 3.f * a.y) * 0.25f,
                           (e.z + 3.f * a.z) * 0.25f,
                           (e.w + 3.f * a.w) * 0.25f);
    __stcs(&reinterpret_cast<float4*>(out)[(size_t)n * 16 + q], m);
}

extern "C" void kernel_launch(void* const* d_in, const int* in_sizes, int n_in,
                              void* d_out, int out_size) {
    const float* ue     = (const float*)d_in[0];
    const float* ie     = (const float*)d_in[1];
    const int*   a_rows = (const int*)  d_in[2];
    const int*   a_cols = (const int*)  d_in[3];
    const float* a_vals = (const float*)d_in[4];
    const int*   r_rows = (const int*)  d_in[5];
    const int*   r_cols = (const int*)  d_in[6];
    const float* r_vals = (const float*)d_in[7];
    float* out = (float*)d_out;

    lgcn_zero<<<(N_CNT + 255) / 256, 256>>>();
    lgcn_hist<<<(NNZ_E + 255) / 256, 256>>>(a_rows, r_rows);
    lgcn_scan<<<dim3(NBLK, 2), SCAN_B>>>();
    lgcn_scatter<<<(NNZ_E + 255) / 256, 256>>>(a_rows, a_cols, a_vals,
                                               r_rows, r_cols, r_vals);
    lgcn_gather<<<(N_CNT * 16 + 255) / 256, 256>>>(ue, ie, out);
}

// round 6
// speedup vs baseline: 1.0402x; 1.0402x over previous
#include <cuda_runtime.h>
#include <cstdint>

#define U_CNT 100000
#define I_CNT 50000
#define DIM   64
#define N_CNT 150000
#define NNZ_E 1000000

#define SCAN_B 1024
#define NBLK   ((N_CNT + SCAN_B - 1) / SCAN_B)   // 147

// ---- static device scratch (no runtime allocation) ----
__device__ int  g_rowptr_a[N_CNT + 1];
__device__ int  g_rowptr_r[N_CNT + 1];
__device__ int  g_cursor_a[N_CNT];
__device__ int  g_cursor_r[N_CNT];
__device__ unsigned int g_tile_a[NBLK];   // decoupled-lookback: (value<<2)|status
__device__ unsigned int g_tile_r[NBLK];   // status: 0 invalid, 1 aggregate, 2 prefix
__device__ int2 g_sorted_a[NNZ_E];        // (col, val bits) grouped by row
__device__ int2 g_sorted_r[NNZ_E];

static __device__ __forceinline__ const float4* ego_row(
    const float* __restrict__ ue, const float* __restrict__ ie, int n) {
    return (n < U_CNT)
        ? reinterpret_cast<const float4*>(ue + (size_t)n * DIM)
        : reinterpret_cast<const float4*>(ie + (size_t)(n - U_CNT) * DIM);
}

static __device__ __forceinline__ void fma4(float4& acc, float v, const float4& x) {
    acc.x = fmaf(v, x.x, acc.x);
    acc.y = fmaf(v, x.y, acc.y);
    acc.z = fmaf(v, x.z, acc.z);
    acc.w = fmaf(v, x.w, acc.w);
}

// K0: zero counters + lookback state (each graph replay must start clean).
__global__ void lgcn_zero() {
    int i = blockIdx.x * blockDim.x + threadIdx.x;
    if (i < N_CNT) { g_rowptr_a[i] = 0; g_rowptr_r[i] = 0; }
    if (i < NBLK)  { g_tile_a[i] = 0u;  g_tile_r[i] = 0u; }
}

// K1: row histogram for both matrices.
__global__ void lgcn_hist(const int* __restrict__ a_rows,
                          const int* __restrict__ r_rows) {
    int i = blockIdx.x * blockDim.x + threadIdx.x;
    if (i < NNZ_E) {
        atomicAdd(&g_rowptr_a[__ldg(&a_rows[i])], 1);
        atomicAdd(&g_rowptr_r[__ldg(&r_rows[i])], 1);
    }
}

// K2: single-pass exclusive scan with decoupled lookback. grid = (NBLK, 2).
__global__ void lgcn_scan() {
    int  m = blockIdx.y;
    int  b = blockIdx.x;
    int  t = threadIdx.x;
    int* cnt = m ? g_rowptr_r : g_rowptr_a;
    int* cur = m ? g_cursor_r : g_cursor_a;
    unsigned int* st = m ? g_tile_r : g_tile_a;

    __shared__ int s[SCAN_B];
    __shared__ int ex_prefix;

    int i = b * SCAN_B + t;
    int v = (i < N_CNT) ? cnt[i] : 0;
    s[t] = v;
    __syncthreads();
    #pragma unroll
    for (int off = 1; off < SCAN_B; off <<= 1) {
        int u = (t >= off) ? s[t - off] : 0;
        __syncthreads();
        s[t] += u;
        __syncthreads();
    }
    int incl  = s[t];
    int total = s[SCAN_B - 1];

    if (t == 0) {
        if (b == 0) {
            ex_prefix = 0;
            atomicExch(&st[0], ((unsigned int)total << 2) | 2u);
        } else {
            atomicExch(&st[b], ((unsigned int)total << 2) | 1u);
            int run = 0;
            for (int j = b - 1; j >= 0; j--) {
                unsigned int x;
                do { x = atomicAdd(&st[j], 0u); } while ((x & 3u) == 0u);
                run += (int)(x >> 2);
                if ((x & 3u) == 2u) break;
            }
            ex_prefix = run;
            atomicExch(&st[b], ((unsigned int)(run + total) << 2) | 2u);
        }
    }
    __syncthreads();

    if (i < N_CNT) {
        int val = ex_prefix + incl - v;   // global exclusive prefix
        cnt[i] = val;
        cur[i] = val;
    }
    if (b == NBLK - 1 && t == SCAN_B - 1) cnt[N_CNT] = NNZ_E;
}

// K3: scatter (col, val) into row-grouped order. 2 edges per matrix per thread:
// 4 independent atomic->store chains (latency-bound; keep regs moderate).
__global__ void lgcn_scatter(const int*  __restrict__ a_rows,
                             const int*  __restrict__ a_cols,
                             const float* __restrict__ a_vals,
                             const int*  __restrict__ r_rows,
                             const int*  __restrict__ r_cols,
                             const float* __restrict__ r_vals) {
    int i = blockIdx.x * blockDim.x + threadIdx.x;   // over NNZ/2
    if (i >= NNZ_E / 2) return;
    int2   ra = __ldg((const int2*)a_rows + i);
    int2   rr = __ldg((const int2*)r_rows + i);
    int2   ca = __ldg((const int2*)a_cols + i);
    int2   cr = __ldg((const int2*)r_cols + i);
    float2 va = __ldg((const float2*)a_vals + i);
    float2 vr = __ldg((const float2*)r_vals + i);
    int pa0 = atomicAdd(&g_cursor_a[ra.x], 1);
    int pa1 = atomicAdd(&g_cursor_a[ra.y], 1);
    int pr0 = atomicAdd(&g_cursor_r[rr.x], 1);
    int pr1 = atomicAdd(&g_cursor_r[rr.y], 1);
    g_sorted_a[pa0] = make_int2(ca.x, __float_as_int(va.x));
    g_sorted_a[pa1] = make_int2(ca.y, __float_as_int(va.y));
    g_sorted_r[pr0] = make_int2(cr.x, __float_as_int(vr.x));
    g_sorted_r[pr1] = make_int2(cr.y, __float_as_int(vr.y));
}

// Unroll-4 CSR row reduction with batched independent loads (R4 winner).
static __device__ __forceinline__ float4 row_reduce(
    const int2* __restrict__ sorted, int s, int e, int q,
    const float* __restrict__ ue, const float* __restrict__ ie) {
    float4 acc = make_float4(0.f, 0.f, 0.f, 0.f);
    int i = s;
    for (; i + 4 <= e; i += 4) {
        int2 c0 = __ldg(&sorted[i]);
        int2 c1 = __ldg(&sorted[i + 1]);
        int2 c2 = __ldg(&sorted[i + 2]);
        int2 c3 = __ldg(&sorted[i + 3]);
        float4 x0 = __ldg(&ego_row(ue, ie, c0.x)[q]);
        float4 x1 = __ldg(&ego_row(ue, ie, c1.x)[q]);
        float4 x2 = __ldg(&ego_row(ue, ie, c2.x)[q]);
        float4 x3 = __ldg(&ego_row(ue, ie, c3.x)[q]);
        fma4(acc, __int_as_float(c0.y), x0);
        fma4(acc, __int_as_float(c1.y), x1);
        fma4(acc, __int_as_float(c2.y), x2);
        fma4(acc, __int_as_float(c3.y), x3);
    }
    if (i < e) {
        int2 c0 = __ldg(&sorted[i]);
        int2 c1 = (i + 1 < e) ? __ldg(&sorted[i + 1]) : make_int2(0, 0);
        int2 c2 = (i + 2 < e) ? __ldg(&sorted[i + 2]) : make_int2(0, 0);
        float4 x0 = __ldg(&ego_row(ue, ie, c0.x)[q]);
        fma4(acc, __int_as_float(c0.y), x0);
        if (i + 1 < e) {
            float4 x1 = __ldg(&ego_row(ue, ie, c1.x)[q]);
            fma4(acc, __int_as_float(c1.y), x1);
        }
        if (i + 2 < e) {
            float4 x2 = __ldg(&ego_row(ue, ie, c2.x)[q]);
            fma4(acc, __int_as_float(c2.y), x2);
        }
    }
    return acc;
}

// K4: per-row gather SpMM + full output emit. Streaming stores (never re-read).
__global__ void lgcn_gather(const float* __restrict__ ue,
                            const float* __restrict__ ie,
                            float* __restrict__ out) {
    int idx = blockIdx.x * blockDim.x + threadIdx.x;
    if (idx >= N_CNT * 16) return;
    int n = idx >> 4;
    int q = idx & 15;

    float4 e = __ldg(&ego_row(ue, ie, n)[q]);

    int s0 = __ldg(&g_rowptr_a[n]);
    int e0 = __ldg(&g_rowptr_a[n + 1]);
    float4 a = row_reduce(g_sorted_a, s0, e0, q, ue, ie);

    int s1 = __ldg(&g_rowptr_r[n]);
    int e1 = __ldg(&g_rowptr_r[n + 1]);
    float4 r = row_reduce(g_sorted_r, s1, e1, q, ue, ie);

    size_t sbase = (size_t)N_CNT * DIM + (size_t)n * 4 * DIM;
    size_t pbase = sbase + (size_t)N_CNT * 4 * DIM;
    float4* s = reinterpret_cast<float4*>(out + sbase);
    float4* p = reinterpret_cast<float4*>(out + pbase);
    __stcs(&s[q],      e);    // stacked slot 0
    __stcs(&s[16 + q], a);    // slots 1..3 identical (reference never updates ego)
    __stcs(&s[32 + q], a);
    __stcs(&s[48 + q], a);
    __stcs(&p[q],      e);
    __stcs(&p[16 + q], r);
    __stcs(&p[32 + q], r);
    __stcs(&p[48 + q], r);

    float4 m = make_float4((e.x + 3.f * a.x) * 0.25f,
                           (e.y + 3.f * a.y) * 0.25f,
                           (e.z + 3.f * a.z) * 0.25f,
                           (e.w + 3.f * a.w) * 0.25f);
    __stcs(&reinterpret_cast<float4*>(out)[(size_t)n * 16 + q], m);
}

extern "C" void kernel_launch(void* const* d_in, const int* in_sizes, int n_in,
                              void* d_out, int out_size) {
    const float* ue     = (const float*)d_in[0];
    const float* ie     = (const float*)d_in[1];
    const int*   a_rows = (const int*)  d_in[2];
    const int*   a_cols = (const int*)  d_in[3];
    const float* a_vals = (const float*)d_in[4];
    const int*   r_rows = (const int*)  d_in[5];
    const int*   r_cols = (const int*)  d_in[6];
    const float* r_vals = (const float*)d_in[7];
    float* out = (float*)d_out;

    lgcn_zero<<<(N_CNT + 255) / 256, 256>>>();
    lgcn_hist<<<(NNZ_E + 255) / 256, 256>>>(a_rows, r_rows);
    lgcn_scan<<<dim3(NBLK, 2), SCAN_B>>>();
    lgcn_scatter<<<(NNZ_E / 2 + 255) / 256, 256>>>(a_rows, a_cols, a_vals,
                                                   r_rows, r_cols, r_vals);
    lgcn_gather<<<(N_CNT * 16 + 255) / 256, 256>>>(ue, ie, out);
}

// round 7
// speedup vs baseline: 1.0550x; 1.0142x over previous
#include <cuda_runtime.h>
#include <cstdint>

#define U_CNT 100000
#define I_CNT 50000
#define DIM   64
#define N_CNT 150000
#define NNZ_E 1000000

#define SCAN_B 1024
#define NBLK   ((N_CNT + SCAN_B - 1) / SCAN_B)   // 147

// ---- static device scratch (no runtime allocation) ----
__device__ int  g_rowptr_a[N_CNT + 1];
__device__ int  g_rowptr_r[N_CNT + 1];
__device__ int  g_rank_a[NNZ_E];          // edge rank within its row (from hist)
__device__ int  g_rank_r[NNZ_E];
__device__ unsigned int g_tile_a[NBLK];   // decoupled-lookback: (value<<2)|status
__device__ unsigned int g_tile_r[NBLK];   // status: 0 invalid, 1 aggregate, 2 prefix
__device__ int2 g_sorted_a[NNZ_E];        // (col, val bits) grouped by row
__device__ int2 g_sorted_r[NNZ_E];

static __device__ __forceinline__ const float4* ego_row(
    const float* __restrict__ ue, const float* __restrict__ ie, int n) {
    return (n < U_CNT)
        ? reinterpret_cast<const float4*>(ue + (size_t)n * DIM)
        : reinterpret_cast<const float4*>(ie + (size_t)(n - U_CNT) * DIM);
}

static __device__ __forceinline__ void fma4(float4& acc, float v, const float4& x) {
    acc.x = fmaf(v, x.x, acc.x);
    acc.y = fmaf(v, x.y, acc.y);
    acc.z = fmaf(v, x.z, acc.z);
    acc.w = fmaf(v, x.w, acc.w);
}

// K0: zero counters + lookback state (each graph replay must start clean).
__global__ void lgcn_zero() {
    int i = blockIdx.x * blockDim.x + threadIdx.x;
    if (i < N_CNT) { g_rowptr_a[i] = 0; g_rowptr_r[i] = 0; }
    if (i < NBLK)  { g_tile_a[i] = 0u;  g_tile_r[i] = 0u; }
}

// K1: row histogram; the atomic's return value IS the edge's rank in its row.
__global__ void lgcn_hist(const int* __restrict__ a_rows,
                          const int* __restrict__ r_rows) {
    int i = blockIdx.x * blockDim.x + threadIdx.x;
    if (i < NNZ_E) {
        g_rank_a[i] = atomicAdd(&g_rowptr_a[__ldg(&a_rows[i])], 1);
        g_rank_r[i] = atomicAdd(&g_rowptr_r[__ldg(&r_rows[i])], 1);
    }
}

// K2: single-pass exclusive scan with decoupled lookback. grid = (NBLK, 2).
__global__ void lgcn_scan() {
    int  m = blockIdx.y;
    int  b = blockIdx.x;
    int  t = threadIdx.x;
    int* cnt = m ? g_rowptr_r : g_rowptr_a;
    unsigned int* st = m ? g_tile_r : g_tile_a;

    __shared__ int s[SCAN_B];
    __shared__ int ex_prefix;

    int i = b * SCAN_B + t;
    int v = (i < N_CNT) ? cnt[i] : 0;
    s[t] = v;
    __syncthreads();
    #pragma unroll
    for (int off = 1; off < SCAN_B; off <<= 1) {
        int u = (t >= off) ? s[t - off] : 0;
        __syncthreads();
        s[t] += u;
        __syncthreads();
    }
    int incl  = s[t];
    int total = s[SCAN_B - 1];

    if (t == 0) {
        if (b == 0) {
            ex_prefix = 0;
            atomicExch(&st[0], ((unsigned int)total << 2) | 2u);
        } else {
            atomicExch(&st[b], ((unsigned int)total << 2) | 1u);
            int run = 0;
            for (int j = b - 1; j >= 0; j--) {
                unsigned int x;
                do { x = atomicAdd(&st[j], 0u); } while ((x & 3u) == 0u);
                run += (int)(x >> 2);
                if ((x & 3u) == 2u) break;
            }
            ex_prefix = run;
            atomicExch(&st[b], ((unsigned int)(run + total) << 2) | 2u);
        }
    }
    __syncthreads();

    if (i < N_CNT) cnt[i] = ex_prefix + incl - v;   // global exclusive prefix
    if (b == NBLK - 1 && t == SCAN_B - 1) cnt[N_CNT] = NNZ_E;
}

// K3: atomic-free scatter — position = rowptr[row] + rank (rank from hist).
__global__ void lgcn_scatter(const int*  __restrict__ a_rows,
                             const int*  __restrict__ a_cols,
                             const float* __restrict__ a_vals,
                             const int*  __restrict__ r_rows,
                             const int*  __restrict__ r_cols,
                             const float* __restrict__ r_vals) {
    int i = blockIdx.x * blockDim.x + threadIdx.x;
    if (i >= NNZ_E) return;
    {
        int row  = __ldg(&a_rows[i]);
        int pos  = __ldg(&g_rowptr_a[row]) + g_rank_a[i];
        g_sorted_a[pos] = make_int2(__ldg(&a_cols[i]),
                                    __float_as_int(__ldg(&a_vals[i])));
    }
    {
        int row  = __ldg(&r_rows[i]);
        int pos  = __ldg(&g_rowptr_r[row]) + g_rank_r[i];
        g_sorted_r[pos] = make_int2(__ldg(&r_cols[i]),
                                    __float_as_int(__ldg(&r_vals[i])));
    }
}

// Unroll-4 CSR row reduction with batched independent loads (R4 winner).
static __device__ __forceinline__ float4 row_reduce(
    const int2* __restrict__ sorted, int s, int e, int q,
    const float* __restrict__ ue, const float* __restrict__ ie) {
    float4 acc = make_float4(0.f, 0.f, 0.f, 0.f);
    int i = s;
    for (; i + 4 <= e; i += 4) {
        int2 c0 = __ldg(&sorted[i]);
        int2 c1 = __ldg(&sorted[i + 1]);
        int2 c2 = __ldg(&sorted[i + 2]);
        int2 c3 = __ldg(&sorted[i + 3]);
        float4 x0 = __ldg(&ego_row(ue, ie, c0.x)[q]);
        float4 x1 = __ldg(&ego_row(ue, ie, c1.x)[q]);
        float4 x2 = __ldg(&ego_row(ue, ie, c2.x)[q]);
        float4 x3 = __ldg(&ego_row(ue, ie, c3.x)[q]);
        fma4(acc, __int_as_float(c0.y), x0);
        fma4(acc, __int_as_float(c1.y), x1);
        fma4(acc, __int_as_float(c2.y), x2);
        fma4(acc, __int_as_float(c3.y), x3);
    }
    if (i < e) {
        int2 c0 = __ldg(&sorted[i]);
        int2 c1 = (i + 1 < e) ? __ldg(&sorted[i + 1]) : make_int2(0, 0);
        int2 c2 = (i + 2 < e) ? __ldg(&sorted[i + 2]) : make_int2(0, 0);
        float4 x0 = __ldg(&ego_row(ue, ie, c0.x)[q]);
        fma4(acc, __int_as_float(c0.y), x0);
        if (i + 1 < e) {
            float4 x1 = __ldg(&ego_row(ue, ie, c1.x)[q]);
            fma4(acc, __int_as_float(c1.y), x1);
        }
        if (i + 2 < e) {
            float4 x2 = __ldg(&ego_row(ue, ie, c2.x)[q]);
            fma4(acc, __int_as_float(c2.y), x2);
        }
    }
    return acc;
}

// K4: per-row gather SpMM + full output emit. Streaming stores (never re-read).
__global__ void lgcn_gather(const float* __restrict__ ue,
                            const float* __restrict__ ie,
                            float* __restrict__ out) {
    int idx = blockIdx.x * blockDim.x + threadIdx.x;
    if (idx >= N_CNT * 16) return;
    int n = idx >> 4;
    int q = idx & 15;

    float4 e = __ldg(&ego_row(ue, ie, n)[q]);

    int s0 = __ldg(&g_rowptr_a[n]);
    int e0 = __ldg(&g_rowptr_a[n + 1]);
    float4 a = row_reduce(g_sorted_a, s0, e0, q, ue, ie);

    int s1 = __ldg(&g_rowptr_r[n]);
    int e1 = __ldg(&g_rowptr_r[n + 1]);
    float4 r = row_reduce(g_sorted_r, s1, e1, q, ue, ie);

    size_t sbase = (size_t)N_CNT * DIM + (size_t)n * 4 * DIM;
    size_t pbase = sbase + (size_t)N_CNT * 4 * DIM;
    float4* s = reinterpret_cast<float4*>(out + sbase);
    float4* p = reinterpret_cast<float4*>(out + pbase);
    __stcs(&s[q],      e);    // stacked slot 0
    __stcs(&s[16 + q], a);    // slots 1..3 identical (reference never updates ego)
    __stcs(&s[32 + q], a);
    __stcs(&s[48 + q], a);
    __stcs(&p[q],      e);
    __stcs(&p[16 + q], r);
    __stcs(&p[32 + q], r);
    __stcs(&p[48 + q], r);

    float4 m = make_float4((e.x + 3.f * a.x) * 0.25f,
                           (e.y + 3.f * a.y) * 0.25f,
                           (e.z + 3.f * a.z) * 0.25f,
                           (e.w + 3.f * a.w) * 0.25f);
    __stcs(&reinterpret_cast<float4*>(out)[(size_t)n * 16 + q], m);
}

extern "C" void kernel_launch(void* const* d_in, const int* in_sizes, int n_in,
                              void* d_out, int out_size) {
    const float* ue     = (const float*)d_in[0];
    const float* ie     = (const float*)d_in[1];
    const int*   a_rows = (const int*)  d_in[2];
    const int*   a_cols = (const int*)  d_in[3];
    const float* a_vals = (const float*)d_in[4];
    const int*   r_rows = (const int*)  d_in[5];
    const int*   r_cols = (const int*)  d_in[6];
    const float* r_vals = (const float*)d_in[7];
    float* out = (float*)d_out;

    lgcn_zero<<<(N_CNT + 255) / 256, 256>>>();
    lgcn_hist<<<(NNZ_E + 255) / 256, 256>>>(a_rows, r_rows);
    lgcn_scan<<<dim3(NBLK, 2), SCAN_B>>>();
    lgcn_scatter<<<(NNZ_E + 255) / 256, 256>>>(a_rows, a_cols, a_vals,
                                               r_rows, r_cols, r_vals);
    lgcn_gather<<<(N_CNT * 16 + 255) / 256, 256>>>(ue, ie, out);
}